// round 7
// baseline (speedup 1.0000x reference)
#include <cuda_runtime.h>
#include <math.h>

#define NB 4
#define KB 2
#define DB 2
#define KI 6
#define DI 5
#define ACCB (KB*(DB+1))   /* 6  */
#define ACCI (KI*(DI+1))   /* 36 */
#define TWO_DELTA_D 6.0f
#define DELTA_V 0.5f
#define PARAM_REG 0.001f
#define MAXLAB (4*512*1024)
#define GX 256             /* x-grid per pass kernel (R1 value, measured fast) */

// ---------------- device scratch (no allocation allowed) --------------------
__device__ float g_bin_acc [NB][ACCB];
__device__ float g_inst_acc[NB][ACCI];
__device__ float g_bin_var [NB][KB];
__device__ float g_inst_var[NB][KI];
__device__ int   g_is64[2];
__device__ unsigned g_cnt;
__device__ unsigned char g_plab_bin [MAXLAB];
__device__ unsigned char g_plab_inst[MAXLAB];

__device__ __forceinline__ float f4c(const float4& v, int p) {
    return p == 0 ? v.x : (p == 1 ? v.y : (p == 2 ? v.z : v.w));
}

// ---------------- kernel 0: zero scratch + PARALLEL dtype detect ------------
__global__ void init_kernel(const int* __restrict__ binlab,
                            const int* __restrict__ instlab) {
    __shared__ int nz[2];
    int t = threadIdx.x;
    if (t == 0) { nz[0] = 0; nz[1] = 0; }
    float* pb = &g_bin_acc[0][0];
    for (int j = t; j < NB*ACCB; j += blockDim.x) pb[j] = 0.f;
    float* pi = &g_inst_acc[0][0];
    for (int j = t; j < NB*ACCI; j += blockDim.x) pi[j] = 0.f;
    float* vb = &g_bin_var[0][0];
    for (int j = t; j < NB*KB; j += blockDim.x) vb[j] = 0.f;
    float* vi = &g_inst_var[0][0];
    for (int j = t; j < NB*KI; j += blockDim.x) vi[j] = 0.f;
    __syncthreads();
    // int64 little-endian => odd 32-bit words of first 64 elems all zero.
    // int32 random labels => P(all zero) <= 2^-64. 64 parallel probes.
    if (t < 64) {
        if (binlab [2*t + 1] != 0) atomicOr(&nz[0], 1);
        if (instlab[2*t + 1] != 0) atomicOr(&nz[1], 1);
    }
    __syncthreads();
    if (t == 0) {
        g_is64[0] = nz[0] ? 0 : 1;
        g_is64[1] = nz[1] ? 0 : 1;
        g_cnt = 0u;
    }
}

// ---------------- pass 1: sums + counts + label packing ---------------------
template<int K, int D>
__global__ __launch_bounds__(256)
void pass1_kernel(const float* __restrict__ logits,
                  const void*  __restrict__ labels,
                  unsigned char* __restrict__ plab,
                  float* __restrict__ gacc,     // [NB][K*(D+1)]
                  int labsel, int MN) {
    constexpr int ACC = K*(D+1);
    const int b = blockIdx.y;
    const float* base = logits + (size_t)b * D * MN;
    const int is64 = g_is64[labsel];
    const int nvec = MN >> 2;
    const size_t lv = (size_t)b * nvec;

    float acc[ACC];
#pragma unroll
    for (int j = 0; j < ACC; j++) acc[j] = 0.f;

    for (int i = blockIdx.x*blockDim.x + threadIdx.x; i < nvec;
         i += gridDim.x*blockDim.x) {
        float4 x[D];
#pragma unroll
        for (int d = 0; d < D; d++)
            x[d] = ((const float4*)(base + (size_t)d*MN))[i];
        int lab[4];
        if (is64) {
            const longlong4 v = ((const longlong4*)labels)[lv + i];
            lab[0]=(int)v.x; lab[1]=(int)v.y; lab[2]=(int)v.z; lab[3]=(int)v.w;
        } else {
            const int4 v = ((const int4*)labels)[lv + i];
            lab[0]=v.x; lab[1]=v.y; lab[2]=v.z; lab[3]=v.w;
        }
        uchar4 pc;
        pc.x = (unsigned char)lab[0]; pc.y = (unsigned char)lab[1];
        pc.z = (unsigned char)lab[2]; pc.w = (unsigned char)lab[3];
        ((uchar4*)plab)[lv + i] = pc;
#pragma unroll
        for (int p = 0; p < 4; p++) {
#pragma unroll
            for (int k = 0; k < K; k++) {
                float m = (lab[p] == k) ? 1.0f : 0.0f;
#pragma unroll
                for (int d = 0; d < D; d++)
                    acc[k*(D+1)+d] = fmaf(m, f4c(x[d], p), acc[k*(D+1)+d]);
                acc[k*(D+1)+D] += m;
            }
        }
    }

#pragma unroll
    for (int j = 0; j < ACC; j++) {
        float v = acc[j];
#pragma unroll
        for (int o = 16; o; o >>= 1) v += __shfl_xor_sync(0xffffffffu, v, o);
        acc[j] = v;
    }
    __shared__ float red[ACC];
    if (threadIdx.x < ACC) red[threadIdx.x] = 0.f;
    __syncthreads();
    if ((threadIdx.x & 31) == 0) {
#pragma unroll
        for (int j = 0; j < ACC; j++) atomicAdd(&red[j], acc[j]);
    }
    __syncthreads();
    if (threadIdx.x < ACC) atomicAdd(&gacc[b*ACC + threadIdx.x], red[threadIdx.x]);
}

// push + reg terms from a [K*D] mean array
template<int K, int D>
__device__ __forceinline__ float rest_terms(const float* mean) {
    float ld = 0.f;
    for (int i = 0; i < K; i++)
        for (int j = 0; j < K; j++) if (i != j) {
            float s = 0.f;
            for (int d = 0; d < D; d++) {
                float df = mean[i*D+d] - mean[j*D+d];
                s += df*df;
            }
            float dn = fmaxf(TWO_DELTA_D - sqrtf(s), 0.f);
            ld += dn*dn;
        }
    ld /= (float)(K*(K-1));
    float lr = 0.f;
    for (int k = 0; k < K; k++) {
        float s = 0.f;
        for (int d = 0; d < D; d++) s += mean[k*D+d]*mean[k*D+d];
        lr += sqrtf(s);
    }
    lr /= (float)K;
    return ld + PARAM_REG * lr;
}

// final combine, run by the globally-last pass-2 CTA (thread 0)
__device__ void final_combine(float* __restrict__ out) {
    float bl = 0.f, il = 0.f;
    for (int bb = 0; bb < NB; bb++) {
        float mb[KB*DB], mi[KI*DI];
        float lvv = 0.f;
        for (int k = 0; k < KB; k++) {
            float c = __ldcg(&g_bin_acc[bb][k*(DB+1)+DB]);
            for (int d = 0; d < DB; d++)
                mb[k*DB+d] = __ldcg(&g_bin_acc[bb][k*(DB+1)+d]) / c;
            lvv += __ldcg(&g_bin_var[bb][k]) / c;
        }
        bl += lvv / (float)KB + rest_terms<KB,DB>(mb);
        float lvi = 0.f;
        for (int k = 0; k < KI; k++) {
            float c = __ldcg(&g_inst_acc[bb][k*(DI+1)+DI]);
            for (int d = 0; d < DI; d++)
                mi[k*DI+d] = __ldcg(&g_inst_acc[bb][k*(DI+1)+d]) / c;
            lvi += __ldcg(&g_inst_var[bb][k]) / c;
        }
        il += lvi / (float)KI + rest_terms<KI,DI>(mi);
    }
    out[0] = bl / (float)NB;
    out[1] = il / (float)NB;
}

// ---------------- pass 2: hinge variance; per-CTA means; last CTA finishes --
template<int K, int D>
__global__ __launch_bounds__(256)
void pass2_kernel(const float* __restrict__ logits,
                  const unsigned char* __restrict__ plab,
                  const float* __restrict__ gacc,    // [NB][K*(D+1)]
                  float* __restrict__ gvar,          // [NB][K]
                  float* __restrict__ out,           // nullptr except inst pass
                  unsigned total_ctas, int MN) {
    const int b = blockIdx.y;
    const float* base = logits + (size_t)b * D * MN;
    const int nvec = MN >> 2;
    const size_t lv = (size_t)b * nvec;

    // per-CTA mean recompute from pass-1 accumulators (kernel boundary = visible)
    __shared__ float smean[K*D];
    if (threadIdx.x < K*D) {
        int k = threadIdx.x / D, d = threadIdx.x % D;
        smean[threadIdx.x] = gacc[b*K*(D+1) + k*(D+1)+d] / gacc[b*K*(D+1) + k*(D+1)+D];
    }
    __syncthreads();

    float accv[K];
#pragma unroll
    for (int k = 0; k < K; k++) accv[k] = 0.f;

    for (int i = blockIdx.x*blockDim.x + threadIdx.x; i < nvec;
         i += gridDim.x*blockDim.x) {
        float4 x[D];
#pragma unroll
        for (int d = 0; d < D; d++)
            x[d] = ((const float4*)(base + (size_t)d*MN))[i];
        const uchar4 pc = ((const uchar4*)plab)[lv + i];
        int lab[4] = {pc.x, pc.y, pc.z, pc.w};
#pragma unroll
        for (int p = 0; p < 4; p++) {
            const float* mu = smean + lab[p]*D;
            float dist2 = 0.f;
#pragma unroll
            for (int d = 0; d < D; d++) {
                float df = f4c(x[d], p) - mu[d];
                dist2 = fmaf(df, df, dist2);
            }
            float h  = fmaxf(sqrtf(dist2) - DELTA_V, 0.f);
            float h2 = h*h;
#pragma unroll
            for (int k = 0; k < K; k++)
                accv[k] += (lab[p] == k) ? h2 : 0.f;
        }
    }

#pragma unroll
    for (int k = 0; k < K; k++) {
        float v = accv[k];
#pragma unroll
        for (int o = 16; o; o >>= 1) v += __shfl_xor_sync(0xffffffffu, v, o);
        accv[k] = v;
    }
    __shared__ float red[K];
    if (threadIdx.x < K) red[threadIdx.x] = 0.f;
    __syncthreads();
    if ((threadIdx.x & 31) == 0) {
#pragma unroll
        for (int k = 0; k < K; k++) atomicAdd(&red[k], accv[k]);
    }
    __syncthreads();
    if (threadIdx.x < K) atomicAdd(&gvar[b*K + threadIdx.x], red[threadIdx.x]);
    __syncthreads();

    // global completion counter across BOTH pass-2 kernels
    if (threadIdx.x == 0) {
        __threadfence();
        unsigned p = atomicAdd(&g_cnt, 1u);
        if (p == total_ctas - 1u) {
            __threadfence();
            final_combine(out);
        }
    }
}

// ---------------- launch -----------------------------------------------------
extern "C" void kernel_launch(void* const* d_in, const int* in_sizes, int n_in,
                              void* d_out, int out_size) {
    const float* bin_logits  = (const float*)d_in[0];
    const void*  bin_labels  = d_in[1];
    const float* inst_logits = (const float*)d_in[2];
    const void*  inst_labels = d_in[3];
    float* out = (float*)d_out;

    const int MN = in_sizes[1] / NB;

    float *p_bin_acc, *p_inst_acc, *p_bin_var, *p_inst_var;
    unsigned char *p_plab_bin, *p_plab_inst;
    cudaGetSymbolAddress((void**)&p_bin_acc,   g_bin_acc);
    cudaGetSymbolAddress((void**)&p_inst_acc,  g_inst_acc);
    cudaGetSymbolAddress((void**)&p_bin_var,   g_bin_var);
    cudaGetSymbolAddress((void**)&p_inst_var,  g_inst_var);
    cudaGetSymbolAddress((void**)&p_plab_bin,  g_plab_bin);
    cudaGetSymbolAddress((void**)&p_plab_inst, g_plab_inst);

    dim3 grid(GX, NB);
    const unsigned total_ctas = 2u * GX * NB;   // both pass-2 kernels combined

    init_kernel<<<1, 256>>>((const int*)bin_labels, (const int*)inst_labels);
    pass1_kernel<KB, DB><<<grid, 256>>>(bin_logits,  bin_labels,  p_plab_bin,  p_bin_acc,  0, MN);
    pass1_kernel<KI, DI><<<grid, 256>>>(inst_logits, inst_labels, p_plab_inst, p_inst_acc, 1, MN);
    pass2_kernel<KB, DB><<<grid, 256>>>(bin_logits,  p_plab_bin,  p_bin_acc,  p_bin_var,  out, total_ctas, MN);
    pass2_kernel<KI, DI><<<grid, 256>>>(inst_logits, p_plab_inst, p_inst_acc, p_inst_var, out, total_ctas, MN);
}